// round 2
// baseline (speedup 1.0000x reference)
#include <cuda_runtime.h>

// Fixed shapes: B=512, N=65536, db4 (L=8)
constexpr int B_SZ   = 512;
constexpr int N_SZ   = 65536;
constexpr int L_FILT = 8;
constexpr int OUTLEN = (N_SZ + L_FILT - 1) / 2;   // 32771
constexpr int PAIRS  = (OUTLEN + 1) / 2;          // 16386 (each thread -> 2 output pairs)
constexpr int TPB    = 256;
constexpr int BLK_X  = (PAIRS + TPB - 1) / TPB;   // 65

// Per-block input span: pairs [T0, T0+256) need x[4*T0-8 .. 4*T0+1031] -> 1040 floats.
// We stage 1040 floats (260 float4) in smem. Halo of 8 on the left, 8 on the right
// relative to the 1024 "core" floats.
constexpr int SMEM_FLOATS = 4 * TPB + 16;          // 1040

// cA[b,j] = sum_k ext[2j+k] * rec_lo[k]
// cD[b,j] = sum_k ext[2j+k] * s_k * rec_lo[7-k],  s_k = +1 (k even), -1 (k odd)
// ext index i = 2j+k maps to x index xi = i - 6, symmetric-reflected at both ends.
__global__ void __launch_bounds__(TPB)
dwt_db4_fused_kernel(const float* __restrict__ x,
                     const float* __restrict__ w,
                     const float* __restrict__ x3,
                     float* __restrict__ cA,
                     float* __restrict__ cD,
                     float* __restrict__ ox3)
{
    __shared__ float sx[SMEM_FLOATS];

    const int b  = blockIdx.y;
    const int bx = blockIdx.x;
    const int tx = threadIdx.x;

    // Fused x3 passthrough (one block per row does it; 8 floats)
    if (bx == 0 && tx < 8) {
        ox3[b * 8 + tx] = x3[b * 8 + tx];
    }

    const float* xr = x + (size_t)b * N_SZ;
    const int T0   = bx * TPB;          // first pair index of this block
    const int gbase = 4 * T0 - 8;       // global x index of sx[0]

    // Stage input span into smem. 260 float4 chunks; chunk c covers x[gbase+4c .. gbase+4c+3].
    // Interior chunks are 16B-aligned in gmem (gbase ≡ 0 mod 4). Boundary chunks
    // (only in first/last block) take the reflected scalar path.
    for (int c = tx; c < SMEM_FLOATS / 4; c += TPB) {
        const int gi = gbase + 4 * c;
        float4 val;
        if (gi >= 0 && gi + 3 < N_SZ) {
            val = *reinterpret_cast<const float4*>(xr + gi);
        } else {
            float tmp[4];
#pragma unroll
            for (int m = 0; m < 4; ++m) {
                int xi = gi + m;
                if (xi < 0)          xi = -1 - xi;
                else if (xi >= N_SZ) xi = 2 * N_SZ - 1 - xi;
                // Guard (last block's tail can exceed 2N-1? No: max gi+3 = 4*PAIRS-8+1039
                // within reflection range). Clamp defensively:
                if (xi < 0) xi = 0; else if (xi >= N_SZ) xi = N_SZ - 1;
                tmp[m] = xr[xi];
            }
            val = make_float4(tmp[0], tmp[1], tmp[2], tmp[3]);
        }
        *reinterpret_cast<float4*>(&sx[4 * c]) = val;
    }

    // Filters (uniform loads, broadcast)
    float hA[8], hD[8];
#pragma unroll
    for (int k = 0; k < 8; ++k) hA[k] = __ldg(w + k);
#pragma unroll
    for (int k = 0; k < 8; ++k) hD[k] = (k & 1) ? -hA[7 - k] : hA[7 - k];

    __syncthreads();

    const int t = T0 + tx;              // pair index
    if (t >= PAIRS) return;

    // sx local window: v[m] = x[4t-8+m] = sx[4*tx + m]
    const float* v = &sx[4 * tx];

    float a0 = 0.f, d0 = 0.f, a1 = 0.f, d1 = 0.f;
#pragma unroll
    for (int k = 0; k < 8; ++k) {
        const float e0 = v[k + 2];      // x[4t-6+k]  -> j0 = 2t
        const float e1 = v[k + 4];      // x[4t-4+k]  -> j1 = 2t+1
        a0 = fmaf(e0, hA[k], a0);
        d0 = fmaf(e0, hD[k], d0);
        a1 = fmaf(e1, hA[k], a1);
        d1 = fmaf(e1, hD[k], d1);
    }

    const size_t orow = (size_t)b * OUTLEN;
    const int j0 = 2 * t;
    cA[orow + j0] = a0;
    cD[orow + j0] = d0;
    if (j0 + 1 < OUTLEN) {
        cA[orow + j0 + 1] = a1;
        cD[orow + j0 + 1] = d1;
    }
}

extern "C" void kernel_launch(void* const* d_in, const int* in_sizes, int n_in,
                              void* d_out, int out_size)
{
    const float* x1 = (const float*)d_in[0];   // (512, 65536)
    // d_in[1] = x2 (unused by reference output)
    const float* x3 = (const float*)d_in[2];   // (512, 1, 8)
    const float* w  = (const float*)d_in[3];   // (8,)

    float* out = (float*)d_out;
    float* cA  = out;                                   // (B, OUTLEN)
    float* cD  = out + (size_t)B_SZ * OUTLEN;           // (B, 1, OUTLEN)
    float* ox3 = out + 2 * (size_t)B_SZ * OUTLEN;       // (B, 1, 8)

    dim3 grid(BLK_X, B_SZ);
    dwt_db4_fused_kernel<<<grid, TPB>>>(x1, w, x3, cA, cD, ox3);
}

// round 3
// speedup vs baseline: 1.2739x; 1.2739x over previous
#include <cuda_runtime.h>

// Fixed shapes: B=512, N=65536, db4 (L=8)
constexpr int B_SZ   = 512;
constexpr int N_SZ   = 65536;
constexpr int OUTLEN = 32771;                      // (N + 8 - 1) / 2
constexpr int PAIRS  = (OUTLEN + 1) / 2;           // 16386
constexpr int TPB    = 256;
constexpr int BLK_X  = (PAIRS + TPB - 1) / TPB;    // 65

__device__ __forceinline__ float4 shfl_up4(float4 v, int delta) {
    float4 r;
    r.x = __shfl_up_sync(0xffffffffu, v.x, delta);
    r.y = __shfl_up_sync(0xffffffffu, v.y, delta);
    r.z = __shfl_up_sync(0xffffffffu, v.z, delta);
    r.w = __shfl_up_sync(0xffffffffu, v.w, delta);
    return r;
}

// cA[b,j] = sum_k ext[2j+k] * rec_lo[k]
// cD[b,j] = sum_k ext[2j+k] * s_k * rec_lo[7-k],  s_k = +1 (k even), -1 (k odd)
// ext index i = 2j+k -> x index xi = i - 6; reflect: xi<0 -> -1-xi ; xi>=N -> 2N-1-xi.
__global__ void __launch_bounds__(TPB)
dwt_db4_kernel(const float* __restrict__ x,
               const float* __restrict__ w,
               const float* __restrict__ x3,
               float* __restrict__ cA,
               float* __restrict__ cD,
               float* __restrict__ ox3)
{
    const int b    = blockIdx.y;
    const int t    = blockIdx.x * blockDim.x + threadIdx.x;   // thread's pair slot
    const int lane = threadIdx.x & 31;

    // Fused x3 passthrough
    if (blockIdx.x == 0 && threadIdx.x < 8)
        ox3[b * 8 + threadIdx.x] = x3[b * 8 + threadIdx.x];

    const float* xr = x + (size_t)b * N_SZ;

    // ---- Gather window x[4t-8 .. 4t+3] into v[12] ----
    // Own dense float4 (clamped for tail lanes so shuffles stay full-warp).
    int a2 = 4 * t; if (a2 + 3 >= N_SZ) a2 = N_SZ - 4;
    float4 r2 = *reinterpret_cast<const float4*>(xr + a2);   // x[4t .. 4t+3]
    float4 r1 = shfl_up4(r2, 1);                             // x[4t-4 .. 4t-1]
    float4 r0 = shfl_up4(r2, 2);                             // x[4t-8 .. 4t-5]
    if (lane < 2) {
        int a0 = 4 * t - 8; if (a0 < 0) a0 = 0;
        r0 = *reinterpret_cast<const float4*>(xr + a0);
        if (lane == 0) {
            int a1 = 4 * t - 4; if (a1 < 0) a1 = 0;
            r1 = *reinterpret_cast<const float4*>(xr + a1);
        }
    }

    float v[12];
    const bool interior = (t >= 2) && (4 * t + 3 < N_SZ);    // t in [2, 16383]
    if (interior) {
        v[0] = r0.x; v[1] = r0.y; v[2]  = r0.z; v[3]  = r0.w;
        v[4] = r1.x; v[5] = r1.y; v[6]  = r1.z; v[7]  = r1.w;
        v[8] = r2.x; v[9] = r2.y; v[10] = r2.z; v[11] = r2.w;
    } else if (t < PAIRS) {
        const int base = 4 * t - 8;
#pragma unroll
        for (int m = 0; m < 12; ++m) {
            int xi = base + m;
            if (xi < 0)          xi = -1 - xi;
            else if (xi >= N_SZ) xi = 2 * N_SZ - 1 - xi;
            v[m] = xr[xi];
        }
    }

    if (t >= PAIRS) return;

    // Filters
    float hA[8], hD[8];
#pragma unroll
    for (int k = 0; k < 8; ++k) hA[k] = __ldg(w + k);
#pragma unroll
    for (int k = 0; k < 8; ++k) hD[k] = (k & 1) ? -hA[7 - k] : hA[7 - k];

    const size_t orowA = (size_t)b * OUTLEN;
    const size_t orowD = orowA;                 // same row offset within cD array
    const int s = (int)(orowA & 1);             // parity shift: j0 = 2t - s is even+orow parity

    float a0 = 0.f, d0 = 0.f, a1 = 0.f, d1 = 0.f;
    if (s == 0) {
        // j0 = 2t: window starts at v[2];  j1 = 2t+1: v[4]
#pragma unroll
        for (int k = 0; k < 8; ++k) {
            a0 = fmaf(v[k + 2], hA[k], a0);
            d0 = fmaf(v[k + 2], hD[k], d0);
            a1 = fmaf(v[k + 4], hA[k], a1);
            d1 = fmaf(v[k + 4], hD[k], d1);
        }
    } else {
        // j0 = 2t-1: window starts at v[0]; j1 = 2t: v[2]
#pragma unroll
        for (int k = 0; k < 8; ++k) {
            a0 = fmaf(v[k],     hA[k], a0);
            d0 = fmaf(v[k],     hD[k], d0);
            a1 = fmaf(v[k + 2], hA[k], a1);
            d1 = fmaf(v[k + 2], hD[k], d1);
        }
    }

    const int j0 = 2 * t - s;
    if (j0 >= 0 && j0 + 1 < OUTLEN) {
        // (orow + j0) is even -> 8B-aligned float2 stores, fully coalesced
        *reinterpret_cast<float2*>(cA + orowA + j0) = make_float2(a0, a1);
        *reinterpret_cast<float2*>(cD + orowD + j0) = make_float2(d0, d1);
    } else {
        // Edges: s==1,t==0 -> only j0+1=0 valid; s==0,t==PAIRS-1 -> only j0=32770 valid
        if (j0 >= 0 && j0 < OUTLEN)         { cA[orowA + j0]     = a0; cD[orowD + j0]     = d0; }
        if (j0 + 1 >= 0 && j0 + 1 < OUTLEN) { cA[orowA + j0 + 1] = a1; cD[orowD + j0 + 1] = d1; }
    }
}

extern "C" void kernel_launch(void* const* d_in, const int* in_sizes, int n_in,
                              void* d_out, int out_size)
{
    const float* x1 = (const float*)d_in[0];   // (512, 65536)
    // d_in[1] = x2 (unused by reference output)
    const float* x3 = (const float*)d_in[2];   // (512, 1, 8)
    const float* w  = (const float*)d_in[3];   // (8,)

    float* out = (float*)d_out;
    float* cA  = out;                                   // (B, OUTLEN)
    float* cD  = out + (size_t)B_SZ * OUTLEN;           // (B, 1, OUTLEN)
    float* ox3 = out + 2 * (size_t)B_SZ * OUTLEN;       // (B, 1, 8)

    dim3 grid(BLK_X, B_SZ);
    dwt_db4_kernel<<<grid, TPB>>>(x1, w, x3, cA, cD, ox3);
}